// round 4
// baseline (speedup 1.0000x reference)
#include <cuda_runtime.h>
#include <math.h>

#define DIM   4096
#define NH    32
#define NKV   8
#define G     4
#define HD    128
#define INTER 14336
#define PS    16
#define B     32
#define QKV_M ((NH + 2*NKV) * HD)   // 6144
#define EPS   1e-5f
#define SCALE 0.08838834764831845f  // 1/sqrt(128)

#define SPLIT 8      // attention split-KV
#define SQKV  8      // split-K qkv  (K=4096 -> 512)
#define SWO   16     // split-K wo   (K=4096 -> 256)
#define SW1   4      // split-K w1   (K=4096 -> 1024)
#define SW2   16     // split-K w2   (K=14336 -> 896)

// ------------------------- device scratch -------------------------
__device__ float g_xaT [DIM * B];
__device__ float g_qkvP[SQKV * QKV_M * B];
__device__ float g_q   [B * NH * HD];
__device__ float g_kn  [B * NKV * HD];
__device__ float g_vn  [B * NKV * HD];
__device__ float g_pO  [B * NKV * SPLIT * G * HD];
__device__ float g_pML [B * NKV * SPLIT * G * 2];
__device__ float g_oT  [NH * HD * B];
__device__ float g_woP [SWO * DIM * B];
__device__ float g_hT  [DIM * B];
__device__ float g_hfT [DIM * B];
__device__ float g_w1P [SW1 * INTER * B];
__device__ float g_gT  [INTER * B];
__device__ float g_w2P [SW2 * DIM * B];

// ------------------------- f32x2 helpers -------------------------
__device__ __forceinline__ unsigned long long pk2(float a, float b) {
    unsigned long long r;
    asm("mov.b64 %0, {%1, %2};" : "=l"(r) : "f"(a), "f"(b));
    return r;
}
__device__ __forceinline__ void fma2(unsigned long long &d,
                                     unsigned long long a,
                                     unsigned long long b) {
    asm("fma.rn.f32x2 %0, %1, %2, %3;" : "=l"(d) : "l"(a), "l"(b), "l"(d));
}
__device__ __forceinline__ void upk2(unsigned long long v, float &a, float &b) {
    asm("mov.b64 {%0, %1}, %2;" : "=f"(a), "=f"(b) : "l"(v));
}

// ------------------------- block reduce (256 threads) -------------------------
__device__ __forceinline__ float blockReduceSum256(float v) {
    __shared__ float sh[8];
    int lane = threadIdx.x & 31, w = threadIdx.x >> 5;
    #pragma unroll
    for (int o = 16; o; o >>= 1) v += __shfl_xor_sync(0xffffffffu, v, o);
    if (lane == 0) sh[w] = v;
    __syncthreads();
    if (threadIdx.x == 0) {
        float total = sh[0];
        #pragma unroll
        for (int i = 1; i < 8; i++) total += sh[i];
        sh[0] = total;
    }
    __syncthreads();
    float total = sh[0];
    __syncthreads();
    return total;
}

// ------------------------- kernel 1: rmsnorm(x) -> xaT -------------------------
__global__ __launch_bounds__(256) void k_rms_x(const float* __restrict__ x,
                                               const float* __restrict__ w) {
    int b = blockIdx.x, tid = threadIdx.x;
    float v[16];
    float ss = 0.f;
    #pragma unroll
    for (int i = 0; i < 16; i++) {
        float t = x[b * DIM + tid + i * 256];
        v[i] = t; ss += t * t;
    }
    ss = blockReduceSum256(ss);
    float r = rsqrtf(ss / (float)DIM + EPS);
    #pragma unroll
    for (int i = 0; i < 16; i++) {
        int m = tid + i * 256;
        g_xaT[m * B + b] = v[i] * r * w[m];
    }
}

// ------------------------- split-K GEMM, register-prefetch pipelined -------------------------
// P[s][m][b] = sum_{k in split s} W[m][k] * XT[k][b]
// BM=128, BK=32, N=32, 256 threads; per-thread 4m(2 pairs) x 4n, f32x2 FMA.
// W tile stored k-major transposed (m-pairs via LDS.64); X stored duplicated
// ((x,x) pairs via LDS.64) -> inner loop is 6 LDS.64 + 8 FFMA2, zero MOVs.
__global__ __launch_bounds__(256) void k_gemm(const float* __restrict__ W,
                                              const float* __restrict__ XT,
                                              float* __restrict__ P,
                                              int M, int K, int kps) {
    __shared__ float Ws[32][130];   // [k][m] transposed
    __shared__ float Xd[32][66];    // [k][2n] duplicated pairs
    const int tid = threadIdx.x;
    const int tx = tid & 7;         // n quad
    const int ty = tid >> 3;        // m quad (0..31)
    const int m0 = blockIdx.x * 128;
    const int kb = blockIdx.y * kps;
    const int ke = kb + kps;

    const int wr = tid >> 3;        // W load row base helper (reused per i)
    const int wc = (tid & 7) * 4;   // W load col
    const int xr = tid >> 3, xc = (tid & 7) * 4;

    float4 wreg[4];
    float4 xreg;

    // ---- prologue: load tile kb ----
    {
        int k0 = kb;
        #pragma unroll
        for (int i = 0; i < 4; i++) {
            int r = i * 32 + wr;
            wreg[i] = *(const float4*)(W + (size_t)(m0 + r) * K + k0 + wc);
        }
        xreg = *(const float4*)(XT + (size_t)(k0 + xr) * B + xc);
    }
    // store tile 0
    #pragma unroll
    for (int i = 0; i < 4; i++) {
        int r = i * 32 + wr;
        Ws[wc + 0][r] = wreg[i].x;
        Ws[wc + 1][r] = wreg[i].y;
        Ws[wc + 2][r] = wreg[i].z;
        Ws[wc + 3][r] = wreg[i].w;
    }
    *(unsigned long long*)&Xd[xr][(xc + 0) * 2] = pk2(xreg.x, xreg.x);
    *(unsigned long long*)&Xd[xr][(xc + 1) * 2] = pk2(xreg.y, xreg.y);
    *(unsigned long long*)&Xd[xr][(xc + 2) * 2] = pk2(xreg.z, xreg.z);
    *(unsigned long long*)&Xd[xr][(xc + 3) * 2] = pk2(xreg.w, xreg.w);
    __syncthreads();

    unsigned long long acc[2][4];
    #pragma unroll
    for (int p = 0; p < 2; p++)
        #pragma unroll
        for (int j = 0; j < 4; j++) acc[p][j] = 0ull;

    for (int k0 = kb + 32; k0 <= ke; k0 += 32) {
        // prefetch next tile into registers (skipped on last iteration)
        if (k0 < ke) {
            #pragma unroll
            for (int i = 0; i < 4; i++) {
                int r = i * 32 + wr;
                wreg[i] = *(const float4*)(W + (size_t)(m0 + r) * K + k0 + wc);
            }
            xreg = *(const float4*)(XT + (size_t)(k0 + xr) * B + xc);
        }
        // compute current tile
        #pragma unroll
        for (int kk = 0; kk < 32; ++kk) {
            unsigned long long w0 = *(const unsigned long long*)&Ws[kk][ty * 4];
            unsigned long long w1 = *(const unsigned long long*)&Ws[kk][ty * 4 + 2];
            unsigned long long x0 = *(const unsigned long long*)&Xd[kk][(tx * 4 + 0) * 2];
            unsigned long long x1 = *(const unsigned long long*)&Xd[kk][(tx * 4 + 1) * 2];
            unsigned long long x2 = *(const unsigned long long*)&Xd[kk][(tx * 4 + 2) * 2];
            unsigned long long x3 = *(const unsigned long long*)&Xd[kk][(tx * 4 + 3) * 2];
            fma2(acc[0][0], w0, x0); fma2(acc[1][0], w1, x0);
            fma2(acc[0][1], w0, x1); fma2(acc[1][1], w1, x1);
            fma2(acc[0][2], w0, x2); fma2(acc[1][2], w1, x2);
            fma2(acc[0][3], w0, x3); fma2(acc[1][3], w1, x3);
        }
        if (k0 < ke) {
            __syncthreads();
            #pragma unroll
            for (int i = 0; i < 4; i++) {
                int r = i * 32 + wr;
                Ws[wc + 0][r] = wreg[i].x;
                Ws[wc + 1][r] = wreg[i].y;
                Ws[wc + 2][r] = wreg[i].z;
                Ws[wc + 3][r] = wreg[i].w;
            }
            *(unsigned long long*)&Xd[xr][(xc + 0) * 2] = pk2(xreg.x, xreg.x);
            *(unsigned long long*)&Xd[xr][(xc + 1) * 2] = pk2(xreg.y, xreg.y);
            *(unsigned long long*)&Xd[xr][(xc + 2) * 2] = pk2(xreg.z, xreg.z);
            *(unsigned long long*)&Xd[xr][(xc + 3) * 2] = pk2(xreg.w, xreg.w);
            __syncthreads();
        }
    }

    // epilogue: m = m0 + ty*4 + p*2 + e, n = tx*4 + j
    #pragma unroll
    for (int p = 0; p < 2; p++) {
        float lo[4], hi[4];
        #pragma unroll
        for (int j = 0; j < 4; j++) upk2(acc[p][j], lo[j], hi[j]);
        size_t mE = (size_t)m0 + ty * 4 + p * 2;
        size_t base = ((size_t)blockIdx.y * M + mE) * B + tx * 4;
        *(float4*)&P[base]     = make_float4(lo[0], lo[1], lo[2], lo[3]);
        *(float4*)&P[base + B] = make_float4(hi[0], hi[1], hi[2], hi[3]);
    }
}

// ------------------------- kernel 3: combine qkv partials + rope -------------------------
__global__ __launch_bounds__(128) void k_rope(const int* __restrict__ offsets) {
    int b = blockIdx.x, hh = blockIdx.y, d = threadIdx.x;
    __shared__ float sm[HD];
    int m = hh * HD + d;
    float v = 0.f;
    #pragma unroll
    for (int s = 0; s < SQKV; s++)
        v += g_qkvP[(size_t)s * QKV_M * B + (size_t)m * B + b];
    sm[d] = v;
    __syncthreads();
    if (hh < NH + NKV) {
        int j = (d & 63);
        double inv = exp(-((double)j / 64.0) * log(10000.0));
        double ang = (double)offsets[b] * inv;
        double si, co;
        sincos(ang, &si, &co);
        float out;
        if (d < 64) out = sm[d] * (float)co - sm[d + 64] * (float)si;
        else        out = sm[d - 64] * (float)si + sm[d] * (float)co;
        if (hh < NH)
            g_q[(size_t)b * NH * HD + hh * HD + d] = out * SCALE;
        else
            g_kn[(size_t)b * NKV * HD + (hh - NH) * HD + d] = out;
    } else {
        g_vn[(size_t)b * NKV * HD + (hh - NH - NKV) * HD + d] = v;
    }
}

// ------------------------- kernel 4: flash attention, split-KV -------------------------
__global__ __launch_bounds__(128) void k_attn(const float* __restrict__ pk,
                                              const float* __restrict__ pv,
                                              const int* __restrict__ pidx,
                                              const int* __restrict__ pindptr,
                                              const int* __restrict__ plast) {
    int s = blockIdx.x, kvh = blockIdx.y, b = blockIdx.z;
    int tid = threadIdx.x, w = tid >> 5, lane = tid & 31;
    __shared__ float smq[G * HD];
    __shared__ float so[4][G][HD];
    __shared__ float sml[4][G][2];

    for (int i = tid; i < G * HD; i += 128)
        smq[i] = g_q[(size_t)b * NH * HD + (kvh * G) * HD + i];
    __syncthreads();
    float4 q[G];
    #pragma unroll
    for (int h = 0; h < G; h++) q[h] = *(float4*)&smq[h * HD + lane * 4];

    int p0 = pindptr[b];
    int npages = pindptr[b + 1] - p0;
    int kvlen = (npages - 1) * PS + plast[b];
    int chunk = (kvlen + SPLIT - 1) / SPLIT;
    int cs = s * chunk, ce = min(cs + chunk, kvlen);
    int kvm1 = kvlen - 1;
    int ce2 = min(ce, kvm1);   // main loop excludes the appended token

    float mv[G], lv[G];
    float4 o[G];
    #pragma unroll
    for (int h = 0; h < G; h++) {
        mv[h] = -1e30f; lv[h] = 0.f; o[h] = make_float4(0.f, 0.f, 0.f, 0.f);
    }

    for (int pos = cs + w * 2; pos < ce2; pos += 8) {
        int pg0 = pidx[p0 + (pos >> 4)];
        size_t ba = (((size_t)pg0 * PS + (pos & 15)) * NKV + kvh) * HD;
        float4 k4a = *(const float4*)(pk + ba + lane * 4);
        float4 v4a = *(const float4*)(pv + ba + lane * 4);
        int pos1 = pos + 1;
        bool h1 = pos1 < ce2;
        float4 k4b = make_float4(0.f, 0.f, 0.f, 0.f);
        float4 v4b = k4b;
        if (h1) {
            int pg1 = pidx[p0 + (pos1 >> 4)];
            size_t bb = (((size_t)pg1 * PS + (pos1 & 15)) * NKV + kvh) * HD;
            k4b = *(const float4*)(pk + bb + lane * 4);
            v4b = *(const float4*)(pv + bb + lane * 4);
        }
        float sa[G], sb[G];
        #pragma unroll
        for (int h = 0; h < G; h++) {
            sa[h] = q[h].x * k4a.x + q[h].y * k4a.y + q[h].z * k4a.z + q[h].w * k4a.w;
            sb[h] = q[h].x * k4b.x + q[h].y * k4b.y + q[h].z * k4b.z + q[h].w * k4b.w;
        }
        #pragma unroll
        for (int off = 16; off; off >>= 1) {
            #pragma unroll
            for (int h = 0; h < G; h++) {
                sa[h] += __shfl_xor_sync(0xffffffffu, sa[h], off);
                sb[h] += __shfl_xor_sync(0xffffffffu, sb[h], off);
            }
        }
        #pragma unroll
        for (int h = 0; h < G; h++) {
            float mn = fmaxf(mv[h], sa[h]);
            float corr = __expf(mv[h] - mn);
            float p = __expf(sa[h] - mn);
            lv[h] = lv[h] * corr + p;
            o[h].x = o[h].x * corr + p * v4a.x;
            o[h].y = o[h].y * corr + p * v4a.y;
            o[h].z = o[h].z * corr + p * v4a.z;
            o[h].w = o[h].w * corr + p * v4a.w;
            mv[h] = mn;
        }
        if (h1) {
            #pragma unroll
            for (int h = 0; h < G; h++) {
                float mn = fmaxf(mv[h], sb[h]);
                float corr = __expf(mv[h] - mn);
                float p = __expf(sb[h] - mn);
                lv[h] = lv[h] * corr + p;
                o[h].x = o[h].x * corr + p * v4b.x;
                o[h].y = o[h].y * corr + p * v4b.y;
                o[h].z = o[h].z * corr + p * v4b.z;
                o[h].w = o[h].w * corr + p * v4b.w;
                mv[h] = mn;
            }
        }
    }

    // appended token (position kvlen-1): warp 0 of the owning split
    if (ce == kvlen && cs < kvlen && w == 0) {
        const float* kp = g_kn + ((size_t)b * NKV + kvh) * HD;
        const float* vp = g_vn + ((size_t)b * NKV + kvh) * HD;
        float4 k4 = *(const float4*)(kp + lane * 4);
        float4 v4 = *(const float4*)(vp + lane * 4);
        float sc[G];
        #pragma unroll
        for (int h = 0; h < G; h++)
            sc[h] = q[h].x * k4.x + q[h].y * k4.y + q[h].z * k4.z + q[h].w * k4.w;
        #pragma unroll
        for (int off = 16; off; off >>= 1)
            #pragma unroll
            for (int h = 0; h < G; h++)
                sc[h] += __shfl_xor_sync(0xffffffffu, sc[h], off);
        #pragma unroll
        for (int h = 0; h < G; h++) {
            float mn = fmaxf(mv[h], sc[h]);
            float corr = __expf(mv[h] - mn);
            float p = __expf(sc[h] - mn);
            lv[h] = lv[h] * corr + p;
            o[h].x = o[h].x * corr + p * v4.x;
            o[h].y = o[h].y * corr + p * v4.y;
            o[h].z = o[h].z * corr + p * v4.z;
            o[h].w = o[h].w * corr + p * v4.w;
            mv[h] = mn;
        }
    }

    #pragma unroll
    for (int h = 0; h < G; h++) {
        so[w][h][lane * 4 + 0] = o[h].x;
        so[w][h][lane * 4 + 1] = o[h].y;
        so[w][h][lane * 4 + 2] = o[h].z;
        so[w][h][lane * 4 + 3] = o[h].w;
        if (lane == 0) { sml[w][h][0] = mv[h]; sml[w][h][1] = lv[h]; }
    }
    __syncthreads();

    size_t pbase = (size_t)(b * NKV + kvh) * SPLIT + s;
    for (int h = 0; h < G; h++) {
        float M = -1e30f;
        #pragma unroll
        for (int ww = 0; ww < 4; ww++) M = fmaxf(M, sml[ww][h][0]);
        float L = 0.f, Od = 0.f;
        #pragma unroll
        for (int ww = 0; ww < 4; ww++) {
            float f = __expf(sml[ww][h][0] - M);
            L += sml[ww][h][1] * f;
            Od += so[ww][h][tid] * f;
        }
        g_pO[(pbase * G + h) * HD + tid] = Od;
        if (tid == 0) {
            g_pML[(pbase * G + h) * 2 + 0] = M;
            g_pML[(pbase * G + h) * 2 + 1] = L;
        }
    }
}

// ------------------------- kernel 5: combine attention splits -> oT -------------------------
__global__ __launch_bounds__(128) void k_attn_comb() {
    int hh = blockIdx.x, b = blockIdx.y, d = threadIdx.x;
    int kvh = hh >> 2, h = hh & 3;
    size_t base0 = (size_t)(b * NKV + kvh) * SPLIT;
    float M = -1e30f;
    #pragma unroll
    for (int s = 0; s < SPLIT; s++)
        M = fmaxf(M, g_pML[((base0 + s) * G + h) * 2]);
    float L = 0.f, Od = 0.f;
    #pragma unroll
    for (int s = 0; s < SPLIT; s++) {
        float f = __expf(g_pML[((base0 + s) * G + h) * 2] - M);
        L += g_pML[((base0 + s) * G + h) * 2 + 1] * f;
        Od += g_pO[((base0 + s) * G + h) * HD + d] * f;
    }
    g_oT[(size_t)(hh * HD + d) * B + b] = Od / L;
}

// ------------------------- kernel 7: h = x + woP; hfT = rmsnorm(h) -------------------------
__global__ __launch_bounds__(256) void k_resid1(const float* __restrict__ x,
                                                const float* __restrict__ fw) {
    int b = blockIdx.x, tid = threadIdx.x;
    float hv[16];
    float ss = 0.f;
    #pragma unroll
    for (int i = 0; i < 16; i++) {
        int m = tid + i * 256;
        float t = x[b * DIM + m];
        #pragma unroll
        for (int s = 0; s < SWO; s++)
            t += g_woP[(size_t)s * DIM * B + (size_t)m * B + b];
        hv[i] = t; ss += t * t;
        g_hT[(size_t)m * B + b] = t;
    }
    ss = blockReduceSum256(ss);
    float r = rsqrtf(ss / (float)DIM + EPS);
    #pragma unroll
    for (int i = 0; i < 16; i++) {
        int m = tid + i * 256;
        g_hfT[(size_t)m * B + b] = hv[i] * r * fw[m];
    }
}

// ------------------------- kernel 9: silu(w1P) * stem -> gT -------------------------
__global__ __launch_bounds__(256) void k_silu(const float* __restrict__ buffer,
                                              const int* __restrict__ bids) {
    int idx = blockIdx.x * 256 + threadIdx.x;   // idx = m*B + b
    int b = idx & 31, m = idx >> 5;
    float v = 0.f;
    #pragma unroll
    for (int s = 0; s < SW1; s++)
        v += g_w1P[(size_t)s * INTER * B + idx];
    float sig = 1.f / (1.f + expf(-v));
    float stem = buffer[(size_t)bids[b] * INTER + m];
    g_gT[idx] = v * sig * stem;
}

// ------------------------- kernel 11: out = h + w2P -------------------------
__global__ __launch_bounds__(256) void k_final(float* __restrict__ out) {
    int idx = blockIdx.x * 256 + threadIdx.x;   // idx = b*DIM + m
    int b = idx >> 12, m = idx & 4095;
    float v = g_hT[(size_t)m * B + b];
    #pragma unroll
    for (int s = 0; s < SW2; s++)
        v += g_w2P[(size_t)s * DIM * B + (size_t)m * B + b];
    out[idx] = v;
}

// ------------------------- launch -------------------------
extern "C" void kernel_launch(void* const* d_in, const int* in_sizes, int n_in,
                              void* d_out, int out_size) {
    (void)in_sizes; (void)n_in; (void)out_size;
    const float* x        = (const float*)d_in[0];
    const float* buffer   = (const float*)d_in[1];
    const float* paged_k  = (const float*)d_in[2];
    const float* paged_v  = (const float*)d_in[3];
    const float* wqkv     = (const float*)d_in[4];
    const float* wo       = (const float*)d_in[5];
    const float* w1       = (const float*)d_in[6];
    const float* w2       = (const float*)d_in[7];
    const float* attn_w   = (const float*)d_in[8];
    const float* ffn_w    = (const float*)d_in[9];
    const int*   bids     = (const int*)d_in[10];
    const int*   offsets  = (const int*)d_in[11];
    const int*   pidx     = (const int*)d_in[13];
    const int*   pindptr  = (const int*)d_in[14];
    const int*   plast    = (const int*)d_in[15];
    float* out = (float*)d_out;

    float* xaT;  cudaGetSymbolAddress((void**)&xaT,  g_xaT);
    float* qkvP; cudaGetSymbolAddress((void**)&qkvP, g_qkvP);
    float* oT;   cudaGetSymbolAddress((void**)&oT,   g_oT);
    float* woP;  cudaGetSymbolAddress((void**)&woP,  g_woP);
    float* hfT;  cudaGetSymbolAddress((void**)&hfT,  g_hfT);
    float* w1P;  cudaGetSymbolAddress((void**)&w1P,  g_w1P);
    float* gT;   cudaGetSymbolAddress((void**)&gT,   g_gT);
    float* w2P;  cudaGetSymbolAddress((void**)&w2P,  g_w2P);

    k_rms_x<<<B, 256>>>(x, attn_w);
    k_gemm<<<dim3(QKV_M / 128, SQKV), 256>>>(wqkv, xaT, qkvP, QKV_M, DIM, DIM / SQKV);
    k_rope<<<dim3(B, 48), 128>>>(offsets);
    k_attn<<<dim3(SPLIT, NKV, B), 128>>>(paged_k, paged_v, pidx, pindptr, plast);
    k_attn_comb<<<dim3(NH, B), 128>>>();
    k_gemm<<<dim3(DIM / 128, SWO), 256>>>(wo, oT, woP, DIM, NH * HD, (NH * HD) / SWO);
    k_resid1<<<B, 256>>>(x, ffn_w);
    k_gemm<<<dim3(INTER / 128, SW1), 256>>>(w1, hfT, w1P, INTER, DIM, DIM / SW1);
    k_silu<<<(INTER * B) / 256, 256>>>(buffer, bids);
    k_gemm<<<dim3(DIM / 128, SW2), 256>>>(w2, gT, w2P, DIM, INTER, INTER / SW2);
    k_final<<<(B * DIM) / 256, 256>>>(out);
}

// round 7
// speedup vs baseline: 2.8083x; 2.8083x over previous
#include <cuda_runtime.h>
#include <math.h>
#include <stdint.h>

#define DIM   4096
#define NH    32
#define NKV   8
#define G     4
#define HD    128
#define INTER 14336
#define PS    16
#define B     32
#define QKV_M ((NH + 2*NKV) * HD)   // 6144
#define EPS   1e-5f
#define SCALE 0.08838834764831845f  // 1/sqrt(128)

#define SPLIT 8      // attention split-KV
#define SQKV  8      // split-K qkv  (K=4096 -> 512)
#define SWO   8      // split-K wo   (K=4096 -> 512)
#define SW1   4      // split-K w1   (K=4096 -> 1024)
#define SW2   8      // split-K w2   (K=14336 -> 1792)

// ------------------------- device scratch -------------------------
__device__ float g_xa  [B * DIM];                  // rmsnorm(x)  [b][k]
__device__ float g_qkvP[SQKV * B * QKV_M];         // qkv partials [s][b][m]
__device__ float g_q   [B * NH * HD];
__device__ float g_kn  [B * NKV * HD];
__device__ float g_vn  [B * NKV * HD];
__device__ float g_pO  [B * NKV * SPLIT * G * HD];
__device__ float g_pML [B * NKV * SPLIT * G * 2];
__device__ float g_o   [B * NH * HD];              // attn out [b][k]
__device__ float g_woP [SWO * B * DIM];
__device__ float g_h   [B * DIM];
__device__ float g_hf  [B * DIM];
__device__ float g_w1P [SW1 * B * INTER];
__device__ float g_g   [B * INTER];
__device__ float g_w2P [SW2 * B * DIM];

// ------------------------- helpers -------------------------
static __device__ __forceinline__ uint32_t f2tf(float f) {
    uint32_t r;
    asm("cvt.rna.tf32.f32 %0, %1;" : "=r"(r) : "f"(f));
    return r;
}
static __device__ __forceinline__ void mma8(float* d,
        uint32_t a0, uint32_t a1, uint32_t a2, uint32_t a3,
        uint32_t b0, uint32_t b1) {
    asm volatile("mma.sync.aligned.m16n8k8.row.col.f32.tf32.tf32.f32 "
        "{%0,%1,%2,%3}, {%4,%5,%6,%7}, {%8,%9}, {%0,%1,%2,%3};"
        : "+f"(d[0]), "+f"(d[1]), "+f"(d[2]), "+f"(d[3])
        : "r"(a0), "r"(a1), "r"(a2), "r"(a3), "r"(b0), "r"(b1));
}

__device__ __forceinline__ float blockReduceSum256(float v) {
    __shared__ float sh[8];
    int lane = threadIdx.x & 31, w = threadIdx.x >> 5;
    #pragma unroll
    for (int o = 16; o; o >>= 1) v += __shfl_xor_sync(0xffffffffu, v, o);
    if (lane == 0) sh[w] = v;
    __syncthreads();
    if (threadIdx.x == 0) {
        float total = sh[0];
        #pragma unroll
        for (int i = 1; i < 8; i++) total += sh[i];
        sh[0] = total;
    }
    __syncthreads();
    float total = sh[0];
    __syncthreads();
    return total;
}

// ------------------------- kernel 1: rmsnorm(x) -> g_xa [b][k] -------------------------
__global__ __launch_bounds__(256) void k_rms_x(const float* __restrict__ x,
                                               const float* __restrict__ w) {
    int b = blockIdx.x, tid = threadIdx.x;
    float v[16];
    float ss = 0.f;
    #pragma unroll
    for (int i = 0; i < 16; i++) {
        float t = x[b * DIM + tid + i * 256];
        v[i] = t; ss += t * t;
    }
    ss = blockReduceSum256(ss);
    float r = rsqrtf(ss / (float)DIM + EPS);
    #pragma unroll
    for (int i = 0; i < 16; i++) {
        int m = tid + i * 256;
        g_xa[(size_t)b * DIM + m] = v[i] * r * w[m];
    }
}

// ------------------------- tf32 mma.sync split-K GEMM -------------------------
// P[(s*B+n)*M + m] = sum_{k in split s} W[m][k] * X[n][k]
// 256 thr, BM=128 (warp owns 16 rows x 32 cols), BK=32, double-buffered SMEM,
// XOR swizzle phi(k)=4*(k>>2); Ws stride 136, Xs stride 40 (conflict-free).
__global__ __launch_bounds__(256) void k_gemm_mma(const float* __restrict__ W,
                                                  const float* __restrict__ X,
                                                  float* __restrict__ P,
                                                  int M, int K, int kps) {
    __shared__ uint32_t Ws[2][32 * 136];
    __shared__ uint32_t Xs[2][32 * 40];
    const int tid = threadIdx.x;
    const int lane = tid & 31, wid = tid >> 5;
    const int wm = wid * 16;
    const int g = lane >> 2, c = lane & 3;
    const int m0 = blockIdx.x * 128;
    const int kb = blockIdx.y * kps;
    const int NC = kps / 32;

    const int sr  = tid >> 3;     // 0..31 (W row group / X batch row)
    const int sc4 = tid & 7;      // float4 column
    const int sph = 4 * sc4;      // phi(k) for staging (k = 4*sc4 + j, j<4)

    float acc[4][4];
    #pragma unroll
    for (int nt = 0; nt < 4; nt++)
        acc[nt][0] = acc[nt][1] = acc[nt][2] = acc[nt][3] = 0.f;

    // ---- stage chunk 0 into buf 0 ----
    {
        const float* wp = W + (size_t)(m0 + sr) * K + kb + sc4 * 4;
        #pragma unroll
        for (int i = 0; i < 4; i++) {
            float4 v = *(const float4*)(wp + (size_t)i * 32 * K);
            int m = i * 32 + sr;
            Ws[0][(sc4 * 4 + 0) * 136 + (m ^ sph)] = f2tf(v.x);
            Ws[0][(sc4 * 4 + 1) * 136 + (m ^ sph)] = f2tf(v.y);
            Ws[0][(sc4 * 4 + 2) * 136 + (m ^ sph)] = f2tf(v.z);
            Ws[0][(sc4 * 4 + 3) * 136 + (m ^ sph)] = f2tf(v.w);
        }
        float4 v = *(const float4*)(X + (size_t)sr * K + kb + sc4 * 4);
        Xs[0][(sc4 * 4 + 0) * 40 + (sr ^ sph)] = f2tf(v.x);
        Xs[0][(sc4 * 4 + 1) * 40 + (sr ^ sph)] = f2tf(v.y);
        Xs[0][(sc4 * 4 + 2) * 40 + (sr ^ sph)] = f2tf(v.z);
        Xs[0][(sc4 * 4 + 3) * 40 + (sr ^ sph)] = f2tf(v.w);
    }
    __syncthreads();

    float4 wv[4], xv;
    for (int cc = 0; cc < NC; cc++) {
        int buf = cc & 1;
        bool more = (cc + 1 < NC);
        if (more) {
            int k0 = kb + (cc + 1) * 32;
            const float* wp = W + (size_t)(m0 + sr) * K + k0 + sc4 * 4;
            #pragma unroll
            for (int i = 0; i < 4; i++)
                wv[i] = *(const float4*)(wp + (size_t)i * 32 * K);
            xv = *(const float4*)(X + (size_t)sr * K + k0 + sc4 * 4);
        }
        const uint32_t* WsB = Ws[buf];
        const uint32_t* XsB = Xs[buf];
        #pragma unroll
        for (int ks = 0; ks < 4; ks++) {
            int kA0 = ks * 8 + c, kA1 = kA0 + 4;
            int ph0 = 8 * ks, ph1 = 8 * ks + 4;
            uint32_t a0 = WsB[kA0 * 136 + ((wm + g)     ^ ph0)];
            uint32_t a1 = WsB[kA0 * 136 + ((wm + g + 8) ^ ph0)];
            uint32_t a2 = WsB[kA1 * 136 + ((wm + g)     ^ ph1)];
            uint32_t a3 = WsB[kA1 * 136 + ((wm + g + 8) ^ ph1)];
            #pragma unroll
            for (int nt = 0; nt < 4; nt++) {
                uint32_t b0 = XsB[kA0 * 40 + ((nt * 8 + g) ^ ph0)];
                uint32_t b1 = XsB[kA1 * 40 + ((nt * 8 + g) ^ ph1)];
                mma8(acc[nt], a0, a1, a2, a3, b0, b1);
            }
        }
        __syncthreads();
        if (more) {
            int ob = buf ^ 1;
            #pragma unroll
            for (int i = 0; i < 4; i++) {
                int m = i * 32 + sr;
                Ws[ob][(sc4 * 4 + 0) * 136 + (m ^ sph)] = f2tf(wv[i].x);
                Ws[ob][(sc4 * 4 + 1) * 136 + (m ^ sph)] = f2tf(wv[i].y);
                Ws[ob][(sc4 * 4 + 2) * 136 + (m ^ sph)] = f2tf(wv[i].z);
                Ws[ob][(sc4 * 4 + 3) * 136 + (m ^ sph)] = f2tf(wv[i].w);
            }
            Xs[ob][(sc4 * 4 + 0) * 40 + (sr ^ sph)] = f2tf(xv.x);
            Xs[ob][(sc4 * 4 + 1) * 40 + (sr ^ sph)] = f2tf(xv.y);
            Xs[ob][(sc4 * 4 + 2) * 40 + (sr ^ sph)] = f2tf(xv.z);
            Xs[ob][(sc4 * 4 + 3) * 40 + (sr ^ sph)] = f2tf(xv.w);
            __syncthreads();
        }
    }

    // epilogue: m16n8k8 C layout -> P[s][n][m]
    float* pb = P + (size_t)blockIdx.y * B * M;
    int mlo = m0 + wm + g;
    #pragma unroll
    for (int nt = 0; nt < 4; nt++) {
        int col = nt * 8 + 2 * c;
        pb[(size_t)(col)     * M + mlo]     = acc[nt][0];
        pb[(size_t)(col + 1) * M + mlo]     = acc[nt][1];
        pb[(size_t)(col)     * M + mlo + 8] = acc[nt][2];
        pb[(size_t)(col + 1) * M + mlo + 8] = acc[nt][3];
    }
}

// ------------------------- kernel 3: combine qkv partials + rope -------------------------
__global__ __launch_bounds__(128) void k_rope(const int* __restrict__ offsets) {
    int b = blockIdx.x, hh = blockIdx.y, d = threadIdx.x;
    __shared__ float sm[HD];
    int m = hh * HD + d;
    float v = 0.f;
    #pragma unroll
    for (int s = 0; s < SQKV; s++)
        v += g_qkvP[((size_t)s * B + b) * QKV_M + m];
    sm[d] = v;
    __syncthreads();
    if (hh < NH + NKV) {
        int j = (d & 63);
        double inv = exp(-((double)j / 64.0) * log(10000.0));
        double ang = (double)offsets[b] * inv;
        double si, co;
        sincos(ang, &si, &co);
        float out;
        if (d < 64) out = sm[d] * (float)co - sm[d + 64] * (float)si;
        else        out = sm[d - 64] * (float)si + sm[d] * (float)co;
        if (hh < NH)
            g_q[(size_t)b * NH * HD + hh * HD + d] = out * SCALE;
        else
            g_kn[(size_t)b * NKV * HD + (hh - NH) * HD + d] = out;
    } else {
        g_vn[(size_t)b * NKV * HD + (hh - NH - NKV) * HD + d] = v;
    }
}

// ------------------------- kernel 4: flash attention, split-KV -------------------------
__global__ __launch_bounds__(128) void k_attn(const float* __restrict__ pk,
                                              const float* __restrict__ pv,
                                              const int* __restrict__ pidx,
                                              const int* __restrict__ pindptr,
                                              const int* __restrict__ plast) {
    int s = blockIdx.x, kvh = blockIdx.y, b = blockIdx.z;
    int tid = threadIdx.x, w = tid >> 5, lane = tid & 31;
    __shared__ float smq[G * HD];
    __shared__ float so[4][G][HD];
    __shared__ float sml[4][G][2];

    for (int i = tid; i < G * HD; i += 128)
        smq[i] = g_q[(size_t)b * NH * HD + (kvh * G) * HD + i];
    __syncthreads();
    float4 q[G];
    #pragma unroll
    for (int h = 0; h < G; h++) q[h] = *(float4*)&smq[h * HD + lane * 4];

    int p0 = pindptr[b];
    int npages = pindptr[b + 1] - p0;
    int kvlen = (npages - 1) * PS + plast[b];
    int chunk = (kvlen + SPLIT - 1) / SPLIT;
    int cs = s * chunk, ce = min(cs + chunk, kvlen);
    int kvm1 = kvlen - 1;
    int ce2 = min(ce, kvm1);

    float mv[G], lv[G];
    float4 o[G];
    #pragma unroll
    for (int h = 0; h < G; h++) {
        mv[h] = -1e30f; lv[h] = 0.f; o[h] = make_float4(0.f, 0.f, 0.f, 0.f);
    }

    for (int pos = cs + w * 2; pos < ce2; pos += 8) {
        int pg0 = pidx[p0 + (pos >> 4)];
        size_t ba = (((size_t)pg0 * PS + (pos & 15)) * NKV + kvh) * HD;
        float4 k4a = *(const float4*)(pk + ba + lane * 4);
        float4 v4a = *(const float4*)(pv + ba + lane * 4);
        int pos1 = pos + 1;
        bool h1 = pos1 < ce2;
        float4 k4b = make_float4(0.f, 0.f, 0.f, 0.f);
        float4 v4b = k4b;
        if (h1) {
            int pg1 = pidx[p0 + (pos1 >> 4)];
            size_t bb = (((size_t)pg1 * PS + (pos1 & 15)) * NKV + kvh) * HD;
            k4b = *(const float4*)(pk + bb + lane * 4);
            v4b = *(const float4*)(pv + bb + lane * 4);
        }
        float sa[G], sb[G];
        #pragma unroll
        for (int h = 0; h < G; h++) {
            sa[h] = q[h].x * k4a.x + q[h].y * k4a.y + q[h].z * k4a.z + q[h].w * k4a.w;
            sb[h] = q[h].x * k4b.x + q[h].y * k4b.y + q[h].z * k4b.z + q[h].w * k4b.w;
        }
        #pragma unroll
        for (int off = 16; off; off >>= 1) {
            #pragma unroll
            for (int h = 0; h < G; h++) {
                sa[h] += __shfl_xor_sync(0xffffffffu, sa[h], off);
                sb[h] += __shfl_xor_sync(0xffffffffu, sb[h], off);
            }
        }
        #pragma unroll
        for (int h = 0; h < G; h++) {
            float mn = fmaxf(mv[h], sa[h]);
            float corr = __expf(mv[h] - mn);
            float p = __expf(sa[h] - mn);
            lv[h] = lv[h] * corr + p;
            o[h].x = o[h].x * corr + p * v4a.x;
            o[h].y = o[h].y * corr + p * v4a.y;
            o[h].z = o[h].z * corr + p * v4a.z;
            o[h].w = o[h].w * corr + p * v4a.w;
            mv[h] = mn;
        }
        if (h1) {
            #pragma unroll
            for (int h = 0; h < G; h++) {
                float mn = fmaxf(mv[h], sb[h]);
                float corr = __expf(mv[h] - mn);
                float p = __expf(sb[h] - mn);
                lv[h] = lv[h] * corr + p;
                o[h].x = o[h].x * corr + p * v4b.x;
                o[h].y = o[h].y * corr + p * v4b.y;
                o[h].z = o[h].z * corr + p * v4b.z;
                o[h].w = o[h].w * corr + p * v4b.w;
                mv[h] = mn;
            }
        }
    }

    if (ce == kvlen && cs < kvlen && w == 0) {
        const float* kp = g_kn + ((size_t)b * NKV + kvh) * HD;
        const float* vp = g_vn + ((size_t)b * NKV + kvh) * HD;
        float4 k4 = *(const float4*)(kp + lane * 4);
        float4 v4 = *(const float4*)(vp + lane * 4);
        float sc[G];
        #pragma unroll
        for (int h = 0; h < G; h++)
            sc[h] = q[h].x * k4.x + q[h].y * k4.y + q[h].z * k4.z + q[h].w * k4.w;
        #pragma unroll
        for (int off = 16; off; off >>= 1)
            #pragma unroll
            for (int h = 0; h < G; h++)
                sc[h] += __shfl_xor_sync(0xffffffffu, sc[h], off);
        #pragma unroll
        for (int h = 0; h < G; h++) {
            float mn = fmaxf(mv[h], sc[h]);
            float corr = __expf(mv[h] - mn);
            float p = __expf(sc[h] - mn);
            lv[h] = lv[h] * corr + p;
            o[h].x = o[h].x * corr + p * v4.x;
            o[h].y = o[h].y * corr + p * v4.y;
            o[h].z = o[h].z * corr + p * v4.z;
            o[h].w = o[h].w * corr + p * v4.w;
            mv[h] = mn;
        }
    }

    #pragma unroll
    for (int h = 0; h < G; h++) {
        so[w][h][lane * 4 + 0] = o[h].x;
        so[w][h][lane * 4 + 1] = o[h].y;
        so[w][h][lane * 4 + 2] = o[h].z;
        so[w][h][lane * 4 + 3] = o[h].w;
        if (lane == 0) { sml[w][h][0] = mv[h]; sml[w][h][1] = lv[h]; }
    }
    __syncthreads();

    size_t pbase = (size_t)(b * NKV + kvh) * SPLIT + s;
    for (int h = 0; h < G; h++) {
        float M = -1e30f;
        #pragma unroll
        for (int ww = 0; ww < 4; ww++) M = fmaxf(M, sml[ww][h][0]);
        float L = 0.f, Od = 0.f;
        #pragma unroll
        for (int ww = 0; ww < 4; ww++) {
            float f = __expf(sml[ww][h][0] - M);
            L += sml[ww][h][1] * f;
            Od += so[ww][h][tid] * f;
        }
        g_pO[(pbase * G + h) * HD + tid] = Od;
        if (tid == 0) {
            g_pML[(pbase * G + h) * 2 + 0] = M;
            g_pML[(pbase * G + h) * 2 + 1] = L;
        }
    }
}

// ------------------------- kernel 5: combine attention splits -> g_o [b][k] -------------------------
__global__ __launch_bounds__(128) void k_attn_comb() {
    int hh = blockIdx.x, b = blockIdx.y, d = threadIdx.x;
    int kvh = hh >> 2, h = hh & 3;
    size_t base0 = (size_t)(b * NKV + kvh) * SPLIT;
    float M = -1e30f;
    #pragma unroll
    for (int s = 0; s < SPLIT; s++)
        M = fmaxf(M, g_pML[((base0 + s) * G + h) * 2]);
    float L = 0.f, Od = 0.f;
    #pragma unroll
    for (int s = 0; s < SPLIT; s++) {
        float f = __expf(g_pML[((base0 + s) * G + h) * 2] - M);
        L += g_pML[((base0 + s) * G + h) * 2 + 1] * f;
        Od += g_pO[((base0 + s) * G + h) * HD + d] * f;
    }
    g_o[(size_t)b * NH * HD + hh * HD + d] = Od / L;
}

// ------------------------- kernel 7: h = x + woP; hf = rmsnorm(h) -------------------------
__global__ __launch_bounds__(256) void k_resid1(const float* __restrict__ x,
                                                const float* __restrict__ fw) {
    int b = blockIdx.x, tid = threadIdx.x;
    float hv[16];
    float ss = 0.f;
    #pragma unroll
    for (int i = 0; i < 16; i++) {
        int m = tid + i * 256;
        float t = x[b * DIM + m];
        #pragma unroll
        for (int s = 0; s < SWO; s++)
            t += g_woP[((size_t)s * B + b) * DIM + m];
        hv[i] = t; ss += t * t;
        g_h[(size_t)b * DIM + m] = t;
    }
    ss = blockReduceSum256(ss);
    float r = rsqrtf(ss / (float)DIM + EPS);
    #pragma unroll
    for (int i = 0; i < 16; i++) {
        int m = tid + i * 256;
        g_hf[(size_t)b * DIM + m] = hv[i] * r * fw[m];
    }
}

// ------------------------- kernel 9: silu(w1P) * stem -> g_g [b][k] -------------------------
__global__ __launch_bounds__(256) void k_silu(const float* __restrict__ buffer,
                                              const int* __restrict__ bids) {
    int m = blockIdx.x * 256 + threadIdx.x;
    int b = blockIdx.y;
    float v = 0.f;
    #pragma unroll
    for (int s = 0; s < SW1; s++)
        v += g_w1P[((size_t)s * B + b) * INTER + m];
    float sig = 1.f / (1.f + expf(-v));
    float stem = buffer[(size_t)bids[b] * INTER + m];
    g_g[(size_t)b * INTER + m] = v * sig * stem;
}

// ------------------------- kernel 11: out = h + w2P -------------------------
__global__ __launch_bounds__(256) void k_final(float* __restrict__ out) {
    int idx = blockIdx.x * 256 + threadIdx.x;   // idx = b*DIM + m
    float v = g_h[idx];
    #pragma unroll
    for (int s = 0; s < SW2; s++)
        v += g_w2P[(size_t)s * B * DIM + idx];
    out[idx] = v;
}

// ------------------------- launch -------------------------
extern "C" void kernel_launch(void* const* d_in, const int* in_sizes, int n_in,
                              void* d_out, int out_size) {
    (void)in_sizes; (void)n_in; (void)out_size;
    const float* x        = (const float*)d_in[0];
    const float* buffer   = (const float*)d_in[1];
    const float* paged_k  = (const float*)d_in[2];
    const float* paged_v  = (const float*)d_in[3];
    const float* wqkv     = (const float*)d_in[4];
    const float* wo       = (const float*)d_in[5];
    const float* w1       = (const float*)d_in[6];
    const float* w2       = (const float*)d_in[7];
    const float* attn_w   = (const float*)d_in[8];
    const float* ffn_w    = (const float*)d_in[9];
    const int*   bids     = (const int*)d_in[10];
    const int*   offsets  = (const int*)d_in[11];
    const int*   pidx     = (const int*)d_in[13];
    const int*   pindptr  = (const int*)d_in[14];
    const int*   plast    = (const int*)d_in[15];
    float* out = (float*)d_out;

    float* xa;   cudaGetSymbolAddress((void**)&xa,   g_xa);
    float* qkvP; cudaGetSymbolAddress((void**)&qkvP, g_qkvP);
    float* oA;   cudaGetSymbolAddress((void**)&oA,   g_o);
    float* woP;  cudaGetSymbolAddress((void**)&woP,  g_woP);
    float* hf;   cudaGetSymbolAddress((void**)&hf,   g_hf);
    float* w1P;  cudaGetSymbolAddress((void**)&w1P,  g_w1P);
    float* gg;   cudaGetSymbolAddress((void**)&gg,   g_g);
    float* w2P;  cudaGetSymbolAddress((void**)&w2P,  g_w2P);

    k_rms_x<<<B, 256>>>(x, attn_w);
    k_gemm_mma<<<dim3(QKV_M / 128, SQKV), 256>>>(wqkv, xa, qkvP, QKV_M, DIM, DIM / SQKV);
    k_rope<<<dim3(B, 48), 128>>>(offsets);
    k_attn<<<dim3(SPLIT, NKV, B), 128>>>(paged_k, paged_v, pidx, pindptr, plast);
    k_attn_comb<<<dim3(NH, B), 128>>>();
    k_gemm_mma<<<dim3(DIM / 128, SWO), 256>>>(wo, oA, woP, DIM, NH * HD, (NH * HD) / SWO);
    k_resid1<<<B, 256>>>(x, ffn_w);
    k_gemm_mma<<<dim3(INTER / 128, SW1), 256>>>(w1, hf, w1P, INTER, DIM, DIM / SW1);
    k_silu<<<dim3(INTER / 256, B), 256>>>(buffer, bids);
    k_gemm_mma<<<dim3(DIM / 128, SW2), 256>>>(w2, gg, w2P, DIM, INTER, INTER / SW2);
    k_final<<<(B * DIM) / 256, 256>>>(out);
}

// round 8
// speedup vs baseline: 3.1888x; 1.1355x over previous
#include <cuda_runtime.h>
#include <math.h>
#include <stdint.h>

#define DIM   4096
#define NH    32
#define NKV   8
#define G     4
#define HD    128
#define INTER 14336
#define PS    16
#define B     32
#define QKV_M ((NH + 2*NKV) * HD)   // 6144
#define EPS   1e-5f
#define SCALE 0.08838834764831845f  // 1/sqrt(128)

#define SPLIT 8      // attention split-KV
#define SQKV  8      // split-K qkv  (K=4096 -> 512)
#define SWO   8      // split-K wo   (K=4096 -> 512)
#define SW1   4      // split-K w1   (K=4096 -> 1024)
#define SW2   8      // split-K w2   (K=14336 -> 1792)

// ------------------------- device scratch -------------------------
__device__ float g_xa  [B * DIM];                  // rmsnorm(x)  [b][k]
__device__ float g_qkvP[SQKV * B * QKV_M];         // qkv partials [s][b][m]
__device__ float g_q   [B * NH * HD];
__device__ float g_kn  [B * NKV * HD];
__device__ float g_vn  [B * NKV * HD];
__device__ float g_pO  [B * NKV * SPLIT * G * HD];
__device__ float g_pML [B * NKV * SPLIT * G * 2];
__device__ float g_o   [B * NH * HD];              // attn out [b][k]
__device__ float g_woP [SWO * B * DIM];
__device__ float g_h   [B * DIM];
__device__ float g_hf  [B * DIM];
__device__ float g_w1P [SW1 * B * INTER];
__device__ float g_g   [B * INTER];
__device__ float g_w2P [SW2 * B * DIM];

// ------------------------- helpers -------------------------
static __device__ __forceinline__ void mma8(float* d,
        uint32_t a0, uint32_t a1, uint32_t a2, uint32_t a3,
        uint32_t b0, uint32_t b1) {
    asm volatile("mma.sync.aligned.m16n8k8.row.col.f32.tf32.tf32.f32 "
        "{%0,%1,%2,%3}, {%4,%5,%6,%7}, {%8,%9}, {%0,%1,%2,%3};"
        : "+f"(d[0]), "+f"(d[1]), "+f"(d[2]), "+f"(d[3])
        : "r"(a0), "r"(a1), "r"(a2), "r"(a3), "r"(b0), "r"(b1));
}
static __device__ __forceinline__ void cpa16(uint32_t s, const void* g) {
    asm volatile("cp.async.cg.shared.global [%0], [%1], 16;" :: "r"(s), "l"(g));
}
static __device__ __forceinline__ uint32_t fbits(float f) {
    return __float_as_uint(f);
}

__device__ __forceinline__ float blockReduceSum256(float v) {
    __shared__ float sh[8];
    int lane = threadIdx.x & 31, w = threadIdx.x >> 5;
    #pragma unroll
    for (int o = 16; o; o >>= 1) v += __shfl_xor_sync(0xffffffffu, v, o);
    if (lane == 0) sh[w] = v;
    __syncthreads();
    if (threadIdx.x == 0) {
        float total = sh[0];
        #pragma unroll
        for (int i = 1; i < 8; i++) total += sh[i];
        sh[0] = total;
    }
    __syncthreads();
    float total = sh[0];
    __syncthreads();
    return total;
}

// ------------------------- kernel 1: rmsnorm(x) -> g_xa [b][k] -------------------------
__global__ __launch_bounds__(256) void k_rms_x(const float* __restrict__ x,
                                               const float* __restrict__ w) {
    int b = blockIdx.x, tid = threadIdx.x;
    float v[16];
    float ss = 0.f;
    #pragma unroll
    for (int i = 0; i < 16; i++) {
        float t = x[b * DIM + tid + i * 256];
        v[i] = t; ss += t * t;
    }
    ss = blockReduceSum256(ss);
    float r = rsqrtf(ss / (float)DIM + EPS);
    #pragma unroll
    for (int i = 0; i < 16; i++) {
        int m = tid + i * 256;
        g_xa[(size_t)b * DIM + m] = v[i] * r * w[m];
    }
}

// ------------------------- tf32 mma.sync split-K GEMM (cp.async staging) ----------
// P[(s*B+n)*M + m] = sum_{k in split s} W[m][k] * X[n][k]
// 256 thr, BM=128, BK=32, [row][k] SMEM layout stride 36 (conflict-free),
// cp.async 16B direct global->shared, double-buffered, raw fp32 bits as tf32.
__global__ __launch_bounds__(256) void k_gemm_mma(const float* __restrict__ W,
                                                  const float* __restrict__ X,
                                                  float* __restrict__ P,
                                                  int M, int K, int kps) {
    __shared__ float Ws[2][128 * 36];
    __shared__ float Xs[2][32 * 36];
    const int tid = threadIdx.x;
    const int lane = tid & 31, wid = tid >> 5;
    const int wm = wid * 16;
    const int g = lane >> 2, c = lane & 3;
    const int m0 = blockIdx.x * 128;
    const int kb = blockIdx.y * kps;
    const int NC = kps / 32;
    const int r = tid >> 3;          // 0..31
    const int j = (tid & 7) * 4;     // k offset of 16B chunk

    float acc[4][4];
    #pragma unroll
    for (int nt = 0; nt < 4; nt++)
        acc[nt][0] = acc[nt][1] = acc[nt][2] = acc[nt][3] = 0.f;

    const uint32_t wd0 = (uint32_t)__cvta_generic_to_shared(&Ws[0][r * 36 + j]);
    const uint32_t wd1 = (uint32_t)__cvta_generic_to_shared(&Ws[1][r * 36 + j]);
    const uint32_t xd0 = (uint32_t)__cvta_generic_to_shared(&Xs[0][r * 36 + j]);
    const uint32_t xd1 = (uint32_t)__cvta_generic_to_shared(&Xs[1][r * 36 + j]);
    const float* wbase = W + (size_t)(m0 + r) * K + j;
    const float* xbase = X + (size_t)r * K + j;

    // stage chunk 0 (buf 0), chunk 1 (buf 1)
    {
        #pragma unroll
        for (int i = 0; i < 4; i++)
            cpa16(wd0 + (uint32_t)i * 32 * 36 * 4, wbase + (size_t)i * 32 * K + kb);
        cpa16(xd0, xbase + kb);
        asm volatile("cp.async.commit_group;" ::: "memory");
    }
    if (NC > 1) {
        #pragma unroll
        for (int i = 0; i < 4; i++)
            cpa16(wd1 + (uint32_t)i * 32 * 36 * 4, wbase + (size_t)i * 32 * K + kb + 32);
        cpa16(xd1, xbase + kb + 32);
        asm volatile("cp.async.commit_group;" ::: "memory");
    }

    for (int cc = 0; cc < NC; cc++) {
        if (cc < NC - 1) asm volatile("cp.async.wait_group 1;" ::: "memory");
        else             asm volatile("cp.async.wait_group 0;" ::: "memory");
        __syncthreads();
        const float* WsB = Ws[cc & 1];
        const float* XsB = Xs[cc & 1];
        #pragma unroll
        for (int ks = 0; ks < 4; ks++) {
            int kA0 = ks * 8 + c, kA1 = kA0 + 4;
            uint32_t a0 = fbits(WsB[(wm + g) * 36 + kA0]);
            uint32_t a1 = fbits(WsB[(wm + g + 8) * 36 + kA0]);
            uint32_t a2 = fbits(WsB[(wm + g) * 36 + kA1]);
            uint32_t a3 = fbits(WsB[(wm + g + 8) * 36 + kA1]);
            #pragma unroll
            for (int nt = 0; nt < 4; nt++) {
                uint32_t b0 = fbits(XsB[(nt * 8 + g) * 36 + kA0]);
                uint32_t b1 = fbits(XsB[(nt * 8 + g) * 36 + kA1]);
                mma8(acc[nt], a0, a1, a2, a3, b0, b1);
            }
        }
        __syncthreads();
        if (cc + 2 < NC) {
            int k0 = kb + (cc + 2) * 32;
            uint32_t wd = (cc & 1) ? wd1 : wd0;
            uint32_t xd = (cc & 1) ? xd1 : xd0;
            #pragma unroll
            for (int i = 0; i < 4; i++)
                cpa16(wd + (uint32_t)i * 32 * 36 * 4, wbase + (size_t)i * 32 * K + k0);
            cpa16(xd, xbase + k0);
            asm volatile("cp.async.commit_group;" ::: "memory");
        }
    }

    // epilogue: m16n8k8 C layout -> P[s][n][m]
    float* pb = P + (size_t)blockIdx.y * B * M;
    int mlo = m0 + wm + g;
    #pragma unroll
    for (int nt = 0; nt < 4; nt++) {
        int col = nt * 8 + 2 * c;
        pb[(size_t)(col)     * M + mlo]     = acc[nt][0];
        pb[(size_t)(col + 1) * M + mlo]     = acc[nt][1];
        pb[(size_t)(col)     * M + mlo + 8] = acc[nt][2];
        pb[(size_t)(col + 1) * M + mlo + 8] = acc[nt][3];
    }
}

// ------------------------- kernel 3: combine qkv partials + rope -------------------------
__global__ __launch_bounds__(128) void k_rope(const int* __restrict__ offsets) {
    int b = blockIdx.x, hh = blockIdx.y, d = threadIdx.x;
    __shared__ float sm[HD];
    int m = hh * HD + d;
    float v = 0.f;
    #pragma unroll
    for (int s = 0; s < SQKV; s++)
        v += g_qkvP[((size_t)s * B + b) * QKV_M + m];
    sm[d] = v;
    __syncthreads();
    if (hh < NH + NKV) {
        int j = (d & 63);
        double inv = exp(-((double)j / 64.0) * log(10000.0));
        double ang = (double)offsets[b] * inv;
        double si, co;
        sincos(ang, &si, &co);
        float out;
        if (d < 64) out = sm[d] * (float)co - sm[d + 64] * (float)si;
        else        out = sm[d - 64] * (float)si + sm[d] * (float)co;
        if (hh < NH)
            g_q[(size_t)b * NH * HD + hh * HD + d] = out * SCALE;
        else
            g_kn[(size_t)b * NKV * HD + (hh - NH) * HD + d] = out;
    } else {
        g_vn[(size_t)b * NKV * HD + (hh - NH - NKV) * HD + d] = v;
    }
}

// ------------------------- kernel 4: flash attention, split-KV, no-rescale ---------
__global__ __launch_bounds__(128) void k_attn(const float* __restrict__ pk,
                                              const float* __restrict__ pv,
                                              const int* __restrict__ pidx,
                                              const int* __restrict__ pindptr,
                                              const int* __restrict__ plast) {
    int s = blockIdx.x, kvh = blockIdx.y, b = blockIdx.z;
    int tid = threadIdx.x, w = tid >> 5, lane = tid & 31;
    __shared__ float smq[G * HD];
    __shared__ float so[4][G][HD];
    __shared__ float sml[4][G][2];

    for (int i = tid; i < G * HD; i += 128)
        smq[i] = g_q[(size_t)b * NH * HD + (kvh * G) * HD + i];
    __syncthreads();
    float4 q[G];
    #pragma unroll
    for (int h = 0; h < G; h++) q[h] = *(float4*)&smq[h * HD + lane * 4];

    int p0 = pindptr[b];
    int npages = pindptr[b + 1] - p0;
    int kvlen = (npages - 1) * PS + plast[b];
    int chunk = (kvlen + SPLIT - 1) / SPLIT;
    int cs = s * chunk, ce = min(cs + chunk, kvlen);
    int kvm1 = kvlen - 1;
    int ce2 = min(ce, kvm1);

    float mv[G], lv[G];
    float4 o[G];
    #pragma unroll
    for (int h = 0; h < G; h++) {
        mv[h] = -1e30f; lv[h] = 0.f; o[h] = make_float4(0.f, 0.f, 0.f, 0.f);
    }

    for (int pos = cs + w * 2; pos < ce2; pos += 8) {
        int pg0 = pidx[p0 + (pos >> 4)];
        size_t ba = (((size_t)pg0 * PS + (pos & 15)) * NKV + kvh) * HD;
        float4 k4a = *(const float4*)(pk + ba + lane * 4);
        float4 v4a = *(const float4*)(pv + ba + lane * 4);
        int pos1 = pos + 1;
        bool h1 = pos1 < ce2;
        float4 k4b = make_float4(0.f, 0.f, 0.f, 0.f);
        float4 v4b = k4b;
        if (h1) {
            int pg1 = pidx[p0 + (pos1 >> 4)];
            size_t bb = (((size_t)pg1 * PS + (pos1 & 15)) * NKV + kvh) * HD;
            k4b = *(const float4*)(pk + bb + lane * 4);
            v4b = *(const float4*)(pv + bb + lane * 4);
        }
        float sa[G], sb[G];
        #pragma unroll
        for (int h = 0; h < G; h++) {
            sa[h] = q[h].x * k4a.x + q[h].y * k4a.y + q[h].z * k4a.z + q[h].w * k4a.w;
            sb[h] = q[h].x * k4b.x + q[h].y * k4b.y + q[h].z * k4b.z + q[h].w * k4b.w;
        }
        #pragma unroll
        for (int off = 16; off; off >>= 1) {
            #pragma unroll
            for (int h = 0; h < G; h++) {
                sa[h] += __shfl_xor_sync(0xffffffffu, sa[h], off);
                sb[h] += __shfl_xor_sync(0xffffffffu, sb[h], off);
            }
        }
        #pragma unroll
        for (int h = 0; h < G; h++) {
            float p = __expf(sa[h]);
            mv[h] = fmaxf(mv[h], sa[h]);
            lv[h] += p;
            o[h].x += p * v4a.x;
            o[h].y += p * v4a.y;
            o[h].z += p * v4a.z;
            o[h].w += p * v4a.w;
        }
        if (h1) {
            #pragma unroll
            for (int h = 0; h < G; h++) {
                float p = __expf(sb[h]);
                mv[h] = fmaxf(mv[h], sb[h]);
                lv[h] += p;
                o[h].x += p * v4b.x;
                o[h].y += p * v4b.y;
                o[h].z += p * v4b.z;
                o[h].w += p * v4b.w;
            }
        }
    }

    // appended token (position kvlen-1): warp 0 of the owning split
    if (ce == kvlen && cs < kvlen && w == 0) {
        const float* kp = g_kn + ((size_t)b * NKV + kvh) * HD;
        const float* vp = g_vn + ((size_t)b * NKV + kvh) * HD;
        float4 k4 = *(const float4*)(kp + lane * 4);
        float4 v4 = *(const float4*)(vp + lane * 4);
        float sc[G];
        #pragma unroll
        for (int h = 0; h < G; h++)
            sc[h] = q[h].x * k4.x + q[h].y * k4.y + q[h].z * k4.z + q[h].w * k4.w;
        #pragma unroll
        for (int off = 16; off; off >>= 1)
            #pragma unroll
            for (int h = 0; h < G; h++)
                sc[h] += __shfl_xor_sync(0xffffffffu, sc[h], off);
        #pragma unroll
        for (int h = 0; h < G; h++) {
            float p = __expf(sc[h]);
            mv[h] = fmaxf(mv[h], sc[h]);
            lv[h] += p;
            o[h].x += p * v4.x;
            o[h].y += p * v4.y;
            o[h].z += p * v4.z;
            o[h].w += p * v4.w;
        }
    }

    #pragma unroll
    for (int h = 0; h < G; h++) {
        so[w][h][lane * 4 + 0] = o[h].x;
        so[w][h][lane * 4 + 1] = o[h].y;
        so[w][h][lane * 4 + 2] = o[h].z;
        so[w][h][lane * 4 + 3] = o[h].w;
        if (lane == 0) { sml[w][h][0] = mv[h]; sml[w][h][1] = lv[h]; }
    }
    __syncthreads();

    // cross-warp: absolute units -> plain sums; convert to (M, L*e^-M) form once.
    size_t pbase = (size_t)(b * NKV + kvh) * SPLIT + s;
    for (int h = 0; h < G; h++) {
        float Mb = fmaxf(fmaxf(sml[0][h][0], sml[1][h][0]),
                         fmaxf(sml[2][h][0], sml[3][h][0]));
        float Ls = sml[0][h][1] + sml[1][h][1] + sml[2][h][1] + sml[3][h][1];
        float Od = so[0][h][tid] + so[1][h][tid] + so[2][h][tid] + so[3][h][tid];
        float scl = __expf(-Mb);
        g_pO[(pbase * G + h) * HD + tid] = Od * scl;
        if (tid == 0) {
            g_pML[(pbase * G + h) * 2 + 0] = Mb;
            g_pML[(pbase * G + h) * 2 + 1] = Ls * scl;
        }
    }
}

// ------------------------- kernel 5: combine attention splits -> g_o [b][k] ----------
__global__ __launch_bounds__(128) void k_attn_comb() {
    int hh = blockIdx.x, b = blockIdx.y, d = threadIdx.x;
    int kvh = hh >> 2, h = hh & 3;
    size_t base0 = (size_t)(b * NKV + kvh) * SPLIT;
    float M = -1e30f;
    #pragma unroll
    for (int s = 0; s < SPLIT; s++)
        M = fmaxf(M, g_pML[((base0 + s) * G + h) * 2]);
    float L = 0.f, Od = 0.f;
    #pragma unroll
    for (int s = 0; s < SPLIT; s++) {
        float f = __expf(g_pML[((base0 + s) * G + h) * 2] - M);
        L += g_pML[((base0 + s) * G + h) * 2 + 1] * f;
        Od += g_pO[((base0 + s) * G + h) * HD + d] * f;
    }
    g_o[(size_t)b * NH * HD + hh * HD + d] = Od / L;
}

// ------------------------- kernel 7: h = x + woP; hf = rmsnorm(h) -------------------------
__global__ __launch_bounds__(256) void k_resid1(const float* __restrict__ x,
                                                const float* __restrict__ fw) {
    int b = blockIdx.x, tid = threadIdx.x;
    float hv[16];
    float ss = 0.f;
    #pragma unroll
    for (int i = 0; i < 16; i++) {
        int m = tid + i * 256;
        float t = x[b * DIM + m];
        #pragma unroll
        for (int s = 0; s < SWO; s++)
            t += g_woP[((size_t)s * B + b) * DIM + m];
        hv[i] = t; ss += t * t;
        g_h[(size_t)b * DIM + m] = t;
    }
    ss = blockReduceSum256(ss);
    float r = rsqrtf(ss / (float)DIM + EPS);
    #pragma unroll
    for (int i = 0; i < 16; i++) {
        int m = tid + i * 256;
        g_hf[(size_t)b * DIM + m] = hv[i] * r * fw[m];
    }
}

// ------------------------- kernel 9: silu(w1P) * stem -> g_g [b][k] -------------------------
__global__ __launch_bounds__(256) void k_silu(const float* __restrict__ buffer,
                                              const int* __restrict__ bids) {
    int m = blockIdx.x * 256 + threadIdx.x;
    int b = blockIdx.y;
    float v = 0.f;
    #pragma unroll
    for (int s = 0; s < SW1; s++)
        v += g_w1P[((size_t)s * B + b) * INTER + m];
    float sig = 1.f / (1.f + expf(-v));
    float stem = buffer[(size_t)bids[b] * INTER + m];
    g_g[(size_t)b * INTER + m] = v * sig * stem;
}

// ------------------------- kernel 11: out = h + w2P -------------------------
__global__ __launch_bounds__(256) void k_final(float* __restrict__ out) {
    int idx = blockIdx.x * 256 + threadIdx.x;   // idx = b*DIM + m
    float v = g_h[idx];
    #pragma unroll
    for (int s = 0; s < SW2; s++)
        v += g_w2P[(size_t)s * B * DIM + idx];
    out[idx] = v;
}

// ------------------------- launch -------------------------
extern "C" void kernel_launch(void* const* d_in, const int* in_sizes, int n_in,
                              void* d_out, int out_size) {
    (void)in_sizes; (void)n_in; (void)out_size;
    const float* x        = (const float*)d_in[0];
    const float* buffer   = (const float*)d_in[1];
    const float* paged_k  = (const float*)d_in[2];
    const float* paged_v  = (const float*)d_in[3];
    const float* wqkv     = (const float*)d_in[4];
    const float* wo       = (const float*)d_in[5];
    const float* w1       = (const float*)d_in[6];
    const float* w2       = (const float*)d_in[7];
    const float* attn_w   = (const float*)d_in[8];
    const float* ffn_w    = (const float*)d_in[9];
    const int*   bids     = (const int*)d_in[10];
    const int*   offsets  = (const int*)d_in[11];
    const int*   pidx     = (const int*)d_in[13];
    const int*   pindptr  = (const int*)d_in[14];
    const int*   plast    = (const int*)d_in[15];
    float* out = (float*)d_out;

    float* xa;   cudaGetSymbolAddress((void**)&xa,   g_xa);
    float* qkvP; cudaGetSymbolAddress((void**)&qkvP, g_qkvP);
    float* oA;   cudaGetSymbolAddress((void**)&oA,   g_o);
    float* woP;  cudaGetSymbolAddress((void**)&woP,  g_woP);
    float* hf;   cudaGetSymbolAddress((void**)&hf,   g_hf);
    float* w1P;  cudaGetSymbolAddress((void**)&w1P,  g_w1P);
    float* gg;   cudaGetSymbolAddress((void**)&gg,   g_g);
    float* w2P;  cudaGetSymbolAddress((void**)&w2P,  g_w2P);

    k_rms_x<<<B, 256>>>(x, attn_w);
    k_gemm_mma<<<dim3(QKV_M / 128, SQKV), 256>>>(wqkv, xa, qkvP, QKV_M, DIM, DIM / SQKV);
    k_rope<<<dim3(B, 48), 128>>>(offsets);
    k_attn<<<dim3(SPLIT, NKV, B), 128>>>(paged_k, paged_v, pidx, pindptr, plast);
    k_attn_comb<<<dim3(NH, B), 128>>>();
    k_gemm_mma<<<dim3(DIM / 128, SWO), 256>>>(wo, oA, woP, DIM, NH * HD, (NH * HD) / SWO);
    k_resid1<<<B, 256>>>(x, ffn_w);
    k_gemm_mma<<<dim3(INTER / 128, SW1), 256>>>(w1, hf, w1P, INTER, DIM, DIM / SW1);
    k_silu<<<dim3(INTER / 256, B), 256>>>(buffer, bids);
    k_gemm_mma<<<dim3(DIM / 128, SW2), 256>>>(w2, gg, w2P, DIM, INTER, INTER / SW2);
    k_final<<<(B * DIM) / 256, 256>>>(out);
}